// round 1
// baseline (speedup 1.0000x reference)
#include <cuda_runtime.h>
#include <math.h>

#define Bz   64
#define Lz   25
#define Fz   128
#define Pz   10000
#define Cz   400
#define BL   1600      // Bz*Lz
#define TOPK 3

// ---------------- scratch (device globals; no allocations allowed) -------------
__device__ __align__(16) float g_buf0[BL * Fz];
__device__ __align__(16) float g_buf1[BL * Fz];
__device__ __align__(16) float g_buf2[BL * Fz];
__device__ __align__(16) float g_buf3[BL * Fz];
__device__ __align__(16) float g_q[BL * Fz];
__device__ __align__(16) float g_k[BL * Fz];
__device__ __align__(16) float g_v[BL * Fz];
__device__ float g_mean[Bz * Lz];
__device__ int   g_idx[TOPK];
__device__ float g_tc[Bz * TOPK];
__device__ unsigned g_maxbits, g_minbits;
__device__ float g_neginv;

// ---------------- embeddings ---------------------------------------------------
__global__ void k_embed(const int* __restrict__ user, const int* __restrict__ poi,
                        const int* __restrict__ cat,  const int* __restrict__ tod,
                        const int* __restrict__ dow,
                        const float* __restrict__ ue,  const float* __restrict__ pe,
                        const float* __restrict__ ce,  const float* __restrict__ te,
                        const float* __restrict__ de,  const float* __restrict__ uec,
                        const float* __restrict__ tec, const float* __restrict__ dec) {
    int r = blockIdx.x, t = threadIdx.x;
    int u = user[r], p = poi[r], c = cat[r], td = tod[r], dw = dow[r];
    g_buf0[r * Fz + t] = ue[u * Fz + t]  + pe[p * Fz + t] + te[td * Fz + t]  + de[dw * Fz + t];
    g_buf1[r * Fz + t] = uec[u * Fz + t] + ce[c * Fz + t] + tec[td * Fz + t] + dec[dw * Fz + t];
}

// ---------------- interval range (min/max over gathered D rows) ---------------
__global__ void k_mm_init() { g_maxbits = 0u; g_minbits = 0x7F7FFFFFu; }

__global__ void k_minmax(const int* __restrict__ poi, const float* __restrict__ Dm) {
    __shared__ float smx[256], smn[256];
    int t = threadIdx.x;
    int row = poi[blockIdx.x];
    const float* rp = Dm + (size_t)row * Pz;
    float mx = -1e30f, mn = 1e30f;
    for (int p = t; p < Pz; p += 256) { float v = rp[p]; mx = fmaxf(mx, v); mn = fminf(mn, v); }
    smx[t] = mx; smn[t] = mn; __syncthreads();
    for (int s = 128; s > 0; s >>= 1) {
        if (t < s) { smx[t] = fmaxf(smx[t], smx[t + s]); smn[t] = fminf(smn[t], smn[t + s]); }
        __syncthreads();
    }
    if (t == 0) {
        // all distances are >= 0 -> float bit pattern order == numeric order
        atomicMax(&g_maxbits, __float_as_uint(smx[0]));
        atomicMin(&g_minbits, __float_as_uint(smn[0]));
    }
}

__global__ void k_range() {
    g_neginv = -1.0f / (__uint_as_float(g_maxbits) - __uint_as_float(g_minbits));
}

// ---------------- q/k/v projection:  dst = in @ W_m^T + b_m -------------------
// grid (50, 3), block 256. blockIdx.y = m (0:q from qx, 1:k from kvx, 2:v from kvx)
__global__ void k_qkv(const float* __restrict__ qx, const float* __restrict__ kvx,
                      const float* __restrict__ Wc, const float* __restrict__ bc) {
    __shared__ __align__(16) float As[32 * Fz];
    int m = blockIdx.y;
    const float* in = (m == 0) ? qx : kvx;
    const float* Wm = Wc + m * Fz * Fz;
    const float* bm = bc + m * Fz;
    float* dst = (m == 0) ? g_q : ((m == 1) ? g_k : g_v);
    int r0 = blockIdx.x * 32;
    int t  = threadIdx.x;
    for (int i = t; i < 32 * Fz; i += 256) As[i] = in[r0 * Fz + i];
    __syncthreads();
    int o = t & 127, rg = t >> 7;     // column o, row-group rg (16 rows)
    float acc[16];
    #pragma unroll
    for (int r = 0; r < 16; r++) acc[r] = 0.f;
    const float4* W4 = (const float4*)(Wm + o * Fz);
    const float4* A4 = (const float4*)(As + (rg * 16) * Fz);
    for (int c = 0; c < 32; c++) {
        float4 w = W4[c];
        #pragma unroll
        for (int r = 0; r < 16; r++) {
            float4 a = A4[r * 32 + c];
            acc[r] += w.x * a.x + w.y * a.y + w.z * a.z + w.w * a.w;
        }
    }
    float bias = bm[o];
    #pragma unroll
    for (int r = 0; r < 16; r++) dst[(r0 + rg * 16 + r) * Fz + o] = acc[r] + bias;
}

// ---------------- channel-mean circular correlation ----------------------------
// corr[b,tau] = (1/128) * sum_{n,d} q[b,(n+tau)%L,d] * k[b,n,d]
// grid 64, block 800 (25 warps: warp = tau)
__global__ void k_corrmean() {
    __shared__ float qs[Lz * Fz], ks[Lz * Fz];
    int b = blockIdx.x, t = threadIdx.x;
    for (int i = t; i < Lz * Fz; i += 800) {
        qs[i] = g_q[b * Lz * Fz + i];
        ks[i] = g_k[b * Lz * Fz + i];
    }
    __syncthreads();
    int tau = t >> 5, lane = t & 31;
    float s = 0.f;
    for (int idx = lane; idx < Lz * Fz; idx += 32) {
        int n = idx >> 7, d = idx & 127;
        int np = n + tau; if (np >= Lz) np -= Lz;
        s += qs[np * Fz + d] * ks[idx];
    }
    for (int o = 16; o > 0; o >>= 1) s += __shfl_down_sync(0xffffffffu, s, o);
    if (lane == 0) g_mean[b * Lz + tau] = s * (1.0f / Fz);
}

// ---------------- top-3 lags + per-batch softmax weights ------------------------
__global__ void k_topk() {
    __shared__ float ms[Bz * Lz];
    __shared__ float gms[Lz];
    __shared__ int   sidx[TOPK];
    int t = threadIdx.x;                    // 64 threads, t == b
    for (int j = 0; j < Lz; j++) ms[t * Lz + j] = g_mean[t * Lz + j];
    __syncthreads();
    if (t < Lz) { float s = 0.f; for (int b = 0; b < Bz; b++) s += ms[b * Lz + t]; gms[t] = s; }
    __syncthreads();
    if (t == 0) {
        for (int kk = 0; kk < TOPK; kk++) {
            float best = -1e38f; int bi = 0;
            for (int j = 0; j < Lz; j++) if (gms[j] > best) { best = gms[j]; bi = j; }
            sidx[kk] = bi; gms[bi] = -1e38f;
        }
    }
    __syncthreads();
    float w0 = ms[t * Lz + sidx[0]], w1 = ms[t * Lz + sidx[1]], w2 = ms[t * Lz + sidx[2]];
    float mx = fmaxf(w0, fmaxf(w1, w2));
    float e0 = expf(w0 - mx), e1 = expf(w1 - mx), e2 = expf(w2 - mx);
    float inv = 1.0f / (e0 + e1 + e2);
    g_tc[t * 3 + 0] = e0 * inv; g_tc[t * 3 + 1] = e1 * inv; g_tc[t * 3 + 2] = e2 * inv;
    if (t < TOPK) g_idx[t] = sidx[t];
}

// ---------------- lag aggregation + output projection ---------------------------
// dst[b,l,:] = ( sum_k v[b,(l+idx_k)%L,:] * tc[b,k] ) @ W3^T + b3
// grid (5, 64), block 128
__global__ void k_aggproj(const float* __restrict__ W3, const float* __restrict__ b3,
                          float* __restrict__ dst) {
    __shared__ __align__(16) float ag[5 * Fz];
    int lg = blockIdx.x, b = blockIdx.y, t = threadIdx.x;
    int l0 = lg * 5;
    int i0 = g_idx[0], i1 = g_idx[1], i2 = g_idx[2];
    float c0 = g_tc[b * 3 + 0], c1 = g_tc[b * 3 + 1], c2 = g_tc[b * 3 + 2];
    const float* vb = g_v + b * Lz * Fz;
    #pragma unroll
    for (int r = 0; r < 5; r++) {
        int l = l0 + r;
        int p0 = l + i0; if (p0 >= Lz) p0 -= Lz;
        int p1 = l + i1; if (p1 >= Lz) p1 -= Lz;
        int p2 = l + i2; if (p2 >= Lz) p2 -= Lz;
        ag[r * Fz + t] = vb[p0 * Fz + t] * c0 + vb[p1 * Fz + t] * c1 + vb[p2 * Fz + t] * c2;
    }
    __syncthreads();
    float acc[5];
    #pragma unroll
    for (int r = 0; r < 5; r++) acc[r] = 0.f;
    const float4* W4 = (const float4*)(W3 + t * Fz);
    const float4* A4 = (const float4*)ag;
    for (int c = 0; c < 32; c++) {
        float4 w = W4[c];
        #pragma unroll
        for (int r = 0; r < 5; r++) {
            float4 a = A4[r * 32 + c];
            acc[r] += w.x * a.x + w.y * a.y + w.z * a.z + w.w * a.w;
        }
    }
    float bias = b3[t];
    #pragma unroll
    for (int r = 0; r < 5; r++) dst[(b * Lz + l0 + r) * Fz + t] = acc[r] + bias;
}

// ---------------- final POI scoring ---------------------------------------------
// pre_poi[b,p] = sum_l (poi_emb[p].out[b,l]) * exp(-D[poi[b,l],p]/range) * vw[l] + vb
// grid (20, 64), block 256, 2 poi columns per thread
__global__ void k_final_poi(const float* __restrict__ outp, const int* __restrict__ poi,
                            const float* __restrict__ pe,   const float* __restrict__ Dm,
                            const float* __restrict__ vw,   const float* __restrict__ vbp,
                            float* __restrict__ dst) {
    __shared__ __align__(16) float outs[Lz * Fz];
    __shared__ float vws[Lz];
    __shared__ int   rows[Lz];
    int b = blockIdx.y, t = threadIdx.x;
    for (int i = t; i < Lz * Fz; i += 256) outs[i] = outp[b * Lz * Fz + i];
    if (t < Lz) { vws[t] = vw[t]; rows[t] = poi[b * Lz + t]; }
    __syncthreads();
    float neginv = g_neginv;
    int p1 = blockIdx.x * 512 + t;
    int p2 = p1 + 256;
    bool ok1 = p1 < Pz, ok2 = p2 < Pz;
    int p1c = ok1 ? p1 : 0, p2c = ok2 ? p2 : 0;
    const float4* pe1 = (const float4*)(pe + (size_t)p1c * Fz);
    const float4* pe2 = (const float4*)(pe + (size_t)p2c * Fz);
    float a1[Lz], a2[Lz];
    #pragma unroll
    for (int l = 0; l < Lz; l++) { a1[l] = 0.f; a2[l] = 0.f; }
    const float4* O4 = (const float4*)outs;
    for (int c = 0; c < 32; c++) {
        float4 x = pe1[c], y = pe2[c];
        #pragma unroll
        for (int l = 0; l < Lz; l++) {
            float4 o = O4[l * 32 + c];
            a1[l] += x.x * o.x + x.y * o.y + x.z * o.z + x.w * o.w;
            a2[l] += y.x * o.x + y.y * o.y + y.z * o.z + y.w * o.w;
        }
    }
    float r1 = 0.f, r2 = 0.f;
    #pragma unroll
    for (int l = 0; l < Lz; l++) {
        const float* drow = Dm + (size_t)rows[l] * Pz;
        float wl = vws[l];
        float d1 = drow[p1c], d2 = drow[p2c];
        r1 += a1[l] * __expf(d1 * neginv) * wl;
        r2 += a2[l] * __expf(d2 * neginv) * wl;
    }
    float bias = vbp[0];
    if (ok1) dst[(size_t)b * Pz + p1] = r1 + bias;
    if (ok2) dst[(size_t)b * Pz + p2] = r2 + bias;
}

// ---------------- final CAT scoring ---------------------------------------------
// pre_cat[b,c] = cat_emb[c] . (sum_l vw[l]*outc[b,l,:]) + vb
// grid 64, block 128
__global__ void k_final_cat(const float* __restrict__ outcp, const float* __restrict__ ce,
                            const float* __restrict__ vw, const float* __restrict__ vbp,
                            float* __restrict__ dst) {
    __shared__ __align__(16) float y[Fz];
    int b = blockIdx.x, t = threadIdx.x;
    float s = 0.f;
    for (int l = 0; l < Lz; l++) s += vw[l] * outcp[(b * Lz + l) * Fz + t];
    y[t] = s;
    __syncthreads();
    const float4* Y4 = (const float4*)y;
    float bias = vbp[0];
    for (int g = 0; g < 4; g++) {
        int c = g * 128 + t;
        if (c < Cz) {
            const float4* C4 = (const float4*)(ce + c * Fz);
            float acc = 0.f;
            for (int q = 0; q < 32; q++) {
                float4 cv = C4[q], yv = Y4[q];
                acc += cv.x * yv.x + cv.y * yv.y + cv.z * yv.z + cv.w * yv.w;
            }
            dst[b * Cz + c] = acc + bias;
        }
    }
}

// ---------------- host driver ----------------------------------------------------
extern "C" void kernel_launch(void* const* d_in, const int* in_sizes, int n_in,
                              void* d_out, int out_size) {
    const int*   user = (const int*)d_in[0];
    const int*   poi  = (const int*)d_in[1];
    const int*   cat  = (const int*)d_in[2];
    const int*   tod  = (const int*)d_in[5];
    const int*   dow  = (const int*)d_in[6];
    const float* ue   = (const float*)d_in[8];
    const float* pe   = (const float*)d_in[9];
    const float* ce   = (const float*)d_in[10];
    const float* te   = (const float*)d_in[11];
    const float* de   = (const float*)d_in[12];
    const float* uec  = (const float*)d_in[13];
    const float* tec  = (const float*)d_in[14];
    const float* dec  = (const float*)d_in[15];
    const float* W    = (const float*)d_in[16];
    const float* Bvv  = (const float*)d_in[17];
    const float* vw   = (const float*)d_in[18];
    const float* vb   = (const float*)d_in[19];
    const float* Dm   = (const float*)d_in[20];
    float* out = (float*)d_out;

    float *b0, *b1, *b2, *b3;
    cudaGetSymbolAddress((void**)&b0, g_buf0);
    cudaGetSymbolAddress((void**)&b1, g_buf1);
    cudaGetSymbolAddress((void**)&b2, g_buf2);
    cudaGetSymbolAddress((void**)&b3, g_buf3);

    k_embed<<<BL, Fz>>>(user, poi, cat, tod, dow, ue, pe, ce, te, de, uec, tec, dec);
    k_mm_init<<<1, 1>>>();
    k_minmax<<<BL, 256>>>(poi, Dm);
    k_range<<<1, 1>>>();

    float* cur_out  = b0;
    float* cur_outc = b1;
    float* spare0   = b2;
    float* spare1   = b3;   (void)spare1;

    for (int i = 0; i < 2; i++) {
        for (int c = 0; c < 4; c++) {
            const float *qx, *kvx;
            if      (c == 0) { qx = cur_out;  kvx = cur_out;  }
            else if (c == 1) { qx = cur_outc; kvx = cur_outc; }
            else if (c == 2) { qx = cur_out;  kvx = cur_outc; }
            else             { qx = cur_outc; kvx = cur_out;  }
            const float* Wc = W   + (size_t)((i * 4 + c) * 4) * Fz * Fz;
            const float* bc = Bvv + (size_t)((i * 4 + c) * 4) * Fz;

            k_qkv<<<dim3(50, 3), 256>>>(qx, kvx, Wc, bc);
            k_corrmean<<<Bz, 800>>>();
            k_topk<<<1, 64>>>();
            float* dst = spare0;
            k_aggproj<<<dim3(5, Bz), 128>>>(Wc + 3 * Fz * Fz, bc + 3 * Fz, dst);

            if (c == 0 || c == 2) { spare0 = cur_out;  cur_out  = dst; }
            else                  { spare0 = cur_outc; cur_outc = dst; }
        }
    }

    k_final_poi<<<dim3(20, Bz), 256>>>(cur_out, poi, pe, Dm, vw, vb, out);
    k_final_cat<<<Bz, 128>>>(cur_outc, ce, vw, vb, out + (size_t)Bz * Pz);
}